// round 2
// baseline (speedup 1.0000x reference)
#include <cuda_runtime.h>
#include <cuda_bf16.h>
#include <stdint.h>

#define TINV 10.0f

__device__ float d_agn[128 * 128];
__device__ float d_ofinv[128 * 1024];
__device__ __nv_bfloat16 d_ofh[128 * 256 * 1024];     // bf16 copy of of (q:0-63, k:64-127)
__device__ float d_xn[2][64 * 1024 * 128];            // normalized x, transposed [b][s][c]
__device__ unsigned long long d_rowbest[64 * 1024];
__device__ unsigned long long d_colbest[64 * 1024];
__device__ double d_gsum, d_dsum;

__device__ __forceinline__ uint32_t fkey(float f) {
    uint32_t u = __float_as_uint(f);
    return (u & 0x80000000u) ? ~u : (u | 0x80000000u);
}
__device__ __forceinline__ unsigned long long packkey(float v, uint32_t idx) {
    return ((unsigned long long)fkey(v) << 32) | (unsigned long long)(0xFFFFFFFFu - idx);
}
__device__ __forceinline__ unsigned long long shflx64(unsigned long long v, int m) {
    return __shfl_xor_sync(0xFFFFFFFFu, v, m);
}
__device__ __forceinline__ void ldsm4t(uint32_t& r0, uint32_t& r1, uint32_t& r2,
                                       uint32_t& r3, uint32_t a) {
    asm volatile("ldmatrix.sync.aligned.m8n8.x4.trans.shared.b16 {%0,%1,%2,%3},[%4];\n"
                 : "=r"(r0), "=r"(r1), "=r"(r2), "=r"(r3) : "r"(a));
}
__device__ __forceinline__ void mma16816(float* c, const uint32_t* a, const uint32_t* b) {
    asm volatile("mma.sync.aligned.m16n8k16.row.col.f32.bf16.bf16.f32 "
                 "{%0,%1,%2,%3},{%4,%5,%6,%7},{%8,%9},{%0,%1,%2,%3};\n"
                 : "+f"(c[0]), "+f"(c[1]), "+f"(c[2]), "+f"(c[3])
                 : "r"(a[0]), "r"(a[1]), "r"(a[2]), "r"(a[3]), "r"(b[0]), "r"(b[1]));
}

__global__ void k_init() {
    int i = blockIdx.x * blockDim.x + threadIdx.x;
    if (i < 64 * 1024) { d_rowbest[i] = 0ULL; d_colbest[i] = 0ULL; }
    if (i == 0) { d_gsum = 0.0; d_dsum = 0.0; }
}

// normalize avgpooled_global rows (128 rows x 128)
__global__ void k_agn(const float* __restrict__ agq, const float* __restrict__ agk) {
    int row = blockIdx.x, c = threadIdx.x;
    const float* src = (row < 64) ? (agq + row * 128) : (agk + (row - 64) * 128);
    float v = src[c];
    __shared__ float red[128];
    red[c] = v * v; __syncthreads();
    for (int off = 64; off; off >>= 1) { if (c < off) red[c] += red[c + off]; __syncthreads(); }
    d_agn[row * 128 + c] = v / fmaxf(sqrtf(red[0]), 1e-12f);
}

// global contrastive loss: one row per block
__global__ void k_global() {
    int i = blockIdx.x, j = threadIdx.x;
    __shared__ float ai[128], red[128], s_pos;
    ai[j] = d_agn[i * 128 + j];
    __syncthreads();
    float dot = 0.0f;
#pragma unroll 8
    for (int c = 0; c < 128; c++) dot += ai[c] * d_agn[j * 128 + c];
    float lg = dot * TINV;
    if (j == ((i + 64) & 127)) s_pos = lg;
    float v = (j == i) ? -1e30f : lg;
    red[j] = v; __syncthreads();
    for (int off = 64; off; off >>= 1) { if (j < off) red[j] = fmaxf(red[j], red[j + off]); __syncthreads(); }
    float mx = red[0]; __syncthreads();
    red[j] = expf(v - mx); __syncthreads();
    for (int off = 64; off; off >>= 1) { if (j < off) red[j] += red[j + off]; __syncthreads(); }
    if (j == 0) atomicAdd(&d_gsum, (double)(logf(red[0]) + mx - s_pos));
}

// of: column inv-norms + bf16 conversion
__global__ void k_prep_of(const float* __restrict__ ofq, const float* __restrict__ ofk) {
    int bb = blockIdx.y;
    int s = blockIdx.x * 256 + threadIdx.x;
    const float* p = (bb < 64) ? (ofq + (size_t)bb * 256 * 1024)
                               : (ofk + (size_t)(bb - 64) * 256 * 1024);
    __nv_bfloat16* o = d_ofh + (size_t)bb * 256 * 1024;
    float acc = 0.0f;
#pragma unroll 4
    for (int d = 0; d < 256; d++) {
        float v = p[(size_t)d * 1024 + s];
        acc += v * v;
        o[(size_t)d * 1024 + s] = __float2bfloat16_rn(v);
    }
    d_ofinv[bb * 1024 + s] = 1.0f / fmaxf(sqrtf(acc), 1e-12f);
}

// x: normalize over C and transpose to [b][s][c]
__global__ void k_prep_x(const float* __restrict__ xq, const float* __restrict__ xk) {
    __shared__ float sh[128 * 33];
    __shared__ float invs[32];
    int bb = blockIdx.y, s0 = blockIdx.x * 32, tid = threadIdx.x;
    const float* src = (bb < 64 ? xq : xk) + (size_t)(bb & 63) * 128 * 1024;
    float* dst = d_xn[bb < 64 ? 0 : 1] + (size_t)(bb & 63) * 1024 * 128;
#pragma unroll
    for (int it = 0; it < 16; it++) {
        int idx = it * 256 + tid, c = idx >> 5, s = idx & 31;
        sh[c * 33 + s] = src[(size_t)c * 1024 + s0 + s];
    }
    __syncthreads();
    if (tid < 32) {
        float acc = 0.0f;
#pragma unroll 8
        for (int c = 0; c < 128; c++) { float v = sh[c * 33 + tid]; acc += v * v; }
        invs[tid] = 1.0f / fmaxf(sqrtf(acc), 1e-12f);
    }
    __syncthreads();
#pragma unroll
    for (int it = 0; it < 16; it++) {
        int idx = it * 256 + tid, s = idx >> 7, c = idx & 127;
        dst[(size_t)(s0 + s) * 128 + c] = sh[c * 33 + s] * invs[s];
    }
}

// batched sim GEMM (bf16 mma) + fused dual argmax
__global__ void __launch_bounds__(256) k_simargmax() {
    int b = blockIdx.z, s0 = blockIdx.y * 128, t0 = blockIdx.x * 128;
    const __nv_bfloat16* Ag = d_ofh + (size_t)b * 256 * 1024;
    const __nv_bfloat16* Bg = d_ofh + (size_t)(64 + b) * 256 * 1024;

    __shared__ __align__(16) uint16_t As[32][136];
    __shared__ __align__(16) uint16_t Bs[32][136];
    __shared__ float qinvs[128], kinvs[128];

    int tid = threadIdx.x;
    if (tid < 128) qinvs[tid] = d_ofinv[b * 1024 + s0 + tid];
    else kinvs[tid - 128] = d_ofinv[(64 + b) * 1024 + t0 + (tid - 128)];

    int lane = tid & 31, w = tid >> 5;
    int wm = w & 1, wn = w >> 1;
    int g = lane >> 2, tg = lane & 3;

    float acc[4][4][4];
#pragma unroll
    for (int mi = 0; mi < 4; mi++)
#pragma unroll
        for (int ni = 0; ni < 4; ni++)
#pragma unroll
            for (int r = 0; r < 4; r++) acc[mi][ni][r] = 0.0f;

    int a_k = (lane & 7) + ((lane >> 4) << 3);
    int a_m = ((lane >> 3) & 1) << 3;
    int b_k = (lane & 7) + (((lane >> 3) & 1) << 3);
    int b_n = (lane >> 4) << 3;

    for (int kc = 0; kc < 8; kc++) {
        __syncthreads();
#pragma unroll
        for (int it = 0; it < 2; it++) {
            int idx = it * 256 + tid, row = idx >> 4, q = idx & 15;
            *(uint4*)&As[row][q * 8] = *(const uint4*)&Ag[(size_t)(kc * 32 + row) * 1024 + s0 + q * 8];
            *(uint4*)&Bs[row][q * 8] = *(const uint4*)&Bg[(size_t)(kc * 32 + row) * 1024 + t0 + q * 8];
        }
        __syncthreads();
#pragma unroll
        for (int kk = 0; kk < 32; kk += 16) {
            uint32_t af[4][4], bf[4][2];
#pragma unroll
            for (int mi = 0; mi < 4; mi++) {
                uint32_t a = (uint32_t)__cvta_generic_to_shared(&As[kk + a_k][wm * 64 + mi * 16 + a_m]);
                ldsm4t(af[mi][0], af[mi][1], af[mi][2], af[mi][3], a);
            }
#pragma unroll
            for (int np = 0; np < 2; np++) {
                uint32_t r0, r1, r2, r3;
                uint32_t a = (uint32_t)__cvta_generic_to_shared(&Bs[kk + b_k][wn * 32 + np * 16 + b_n]);
                ldsm4t(r0, r1, r2, r3, a);
                bf[np * 2][0] = r0; bf[np * 2][1] = r1;
                bf[np * 2 + 1][0] = r2; bf[np * 2 + 1][1] = r3;
            }
#pragma unroll
            for (int mi = 0; mi < 4; mi++)
#pragma unroll
                for (int ni = 0; ni < 4; ni++)
                    mma16816(acc[mi][ni], af[mi], bf[ni]);
        }
    }

    // row argmax (over t, scale kinv[t])
#pragma unroll
    for (int mi = 0; mi < 4; mi++)
#pragma unroll
        for (int rh = 0; rh < 2; rh++) {
            unsigned long long best = 0ULL;
#pragma unroll
            for (int ni = 0; ni < 4; ni++)
#pragma unroll
                for (int cp = 0; cp < 2; cp++) {
                    int tl = wn * 32 + ni * 8 + 2 * tg + cp;
                    unsigned long long k2 = packkey(acc[mi][ni][rh * 2 + cp] * kinvs[tl],
                                                   (uint32_t)(t0 + tl));
                    best = (k2 > best) ? k2 : best;
                }
            unsigned long long o;
            o = shflx64(best, 1); best = (o > best) ? o : best;
            o = shflx64(best, 2); best = (o > best) ? o : best;
            if (tg == 0) {
                int sl = wm * 64 + mi * 16 + g + 8 * rh;
                atomicMax(&d_rowbest[b * 1024 + s0 + sl], best);
            }
        }
    // col argmax (over s, scale qinv[s])
#pragma unroll
    for (int ni = 0; ni < 4; ni++)
#pragma unroll
        for (int cp = 0; cp < 2; cp++) {
            int tl = wn * 32 + ni * 8 + 2 * tg + cp;
            unsigned long long best = 0ULL;
#pragma unroll
            for (int mi = 0; mi < 4; mi++)
#pragma unroll
                for (int rh = 0; rh < 2; rh++) {
                    int sl = wm * 64 + mi * 16 + g + 8 * rh;
                    unsigned long long k2 = packkey(acc[mi][ni][rh * 2 + cp] * qinvs[sl],
                                                   (uint32_t)(s0 + sl));
                    best = (k2 > best) ? k2 : best;
                }
            unsigned long long o;
            o = shflx64(best, 4);  best = (o > best) ? o : best;
            o = shflx64(best, 8);  best = (o > best) ? o : best;
            o = shflx64(best, 16); best = (o > best) ? o : best;
            if (g == 0) atomicMax(&d_colbest[b * 1024 + t0 + tl], best);
        }
}

// dense losses: neg GEMM (128s x 64j over C=128) + pos gather + CE, per (s-tile, b, dir)
__global__ void __launch_bounds__(256) k_dense(const float* __restrict__ adq,
                                               const float* __restrict__ adk) {
    int b = blockIdx.y, dir = blockIdx.z, s0 = blockIdx.x * 128;
    const float* xA = d_xn[dir] + (size_t)b * 1024 * 128;
    const float* xB = d_xn[dir ^ 1] + (size_t)b * 1024 * 128;
    const float* ad = dir ? adq : adk;
    const unsigned long long* best = dir ? d_colbest : d_rowbest;

    __shared__ __align__(16) float sbuf[128 * 64 + 128];
    float* Ls = sbuf;
    float* posv = sbuf + 128 * 64;
    float* xs = sbuf;              // phase1 alias: [128][33]
    float* ads = sbuf + 128 * 33;  // phase1 alias: [64][33]

    int tid = threadIdx.x, sg = tid >> 3, jg = tid & 7;
    float accL[4][8];
#pragma unroll
    for (int i = 0; i < 4; i++)
#pragma unroll
        for (int k = 0; k < 8; k++) accL[i][k] = 0.0f;

    for (int cc = 0; cc < 4; cc++) {
        __syncthreads();
        int c0 = cc * 32;
#pragma unroll
        for (int it = 0; it < 16; it++) {
            int idx = it * 256 + tid, r = idx >> 5, c = idx & 31;
            xs[r * 33 + c] = xA[(size_t)(s0 + r) * 128 + c0 + c];
        }
#pragma unroll
        for (int it = 0; it < 8; it++) {
            int idx = it * 256 + tid, j = idx >> 5, c = idx & 31;
            ads[j * 33 + c] = ad[j * 128 + c0 + c];
        }
        __syncthreads();
#pragma unroll 4
        for (int c = 0; c < 32; c++) {
            float a[4], bb[8];
#pragma unroll
            for (int i = 0; i < 4; i++) a[i] = xs[(sg * 4 + i) * 33 + c];
#pragma unroll
            for (int k = 0; k < 8; k++) bb[k] = ads[(jg * 8 + k) * 33 + c];
#pragma unroll
            for (int i = 0; i < 4; i++)
#pragma unroll
                for (int k = 0; k < 8; k++) accL[i][k] += a[i] * bb[k];
        }
    }
    __syncthreads();
#pragma unroll
    for (int i = 0; i < 4; i++)
#pragma unroll
        for (int k = 0; k < 8; k++)
            Ls[(sg * 4 + i) * 64 + jg * 8 + k] = accL[i][k] * TINV;

    int lane = tid & 31, w = tid >> 5;
    for (int rr = 0; rr < 16; rr++) {
        int r = w * 16 + rr, sgl = s0 + r;
        unsigned long long bk = best[b * 1024 + sgl];
        int ind = (int)(0xFFFFFFFFu - (uint32_t)(bk & 0xFFFFFFFFull));
        float sum = 0.0f;
#pragma unroll
        for (int c = lane; c < 128; c += 32)
            sum += xA[(size_t)sgl * 128 + c] * xB[(size_t)ind * 128 + c];
#pragma unroll
        for (int off = 16; off; off >>= 1) sum += __shfl_xor_sync(0xFFFFFFFFu, sum, off);
        if (lane == 0) posv[r] = sum * TINV;
    }
    __syncthreads();

    float wsum = 0.0f;
    for (int rr = 0; rr < 16; rr++) {
        int r = w * 16 + rr;
        float v0 = Ls[r * 64 + lane], v1 = Ls[r * 64 + lane + 32];
        if (lane == b) v0 = -1e30f;
        if (lane + 32 == b) v1 = -1e30f;
        float pos = posv[r];
        float mx = fmaxf(fmaxf(v0, v1), pos);
#pragma unroll
        for (int off = 16; off; off >>= 1) mx = fmaxf(mx, __shfl_xor_sync(0xFFFFFFFFu, mx, off));
        float e = expf(v0 - mx) + expf(v1 - mx);
#pragma unroll
        for (int off = 16; off; off >>= 1) e += __shfl_xor_sync(0xFFFFFFFFu, e, off);
        if (lane == 0) wsum += logf(e + expf(pos - mx)) + mx - pos;
    }
    if (lane == 0) atomicAdd(&d_dsum, (double)wsum);
}

__global__ void k_final(const int* __restrict__ epoch, float* __restrict__ out) {
    float g = (float)(d_gsum / 128.0);
    float d = (float)(d_dsum / 131072.0);
    out[0] = (*epoch > 0) ? (0.5f * g + 0.5f * d) : g;
}

extern "C" void kernel_launch(void* const* d_in, const int* in_sizes, int n_in,
                              void* d_out, int out_size) {
    const float* ofq = (const float*)d_in[0];
    const float* agq = (const float*)d_in[1];
    const float* xq  = (const float*)d_in[2];
    const float* adq = (const float*)d_in[3];
    const float* ofk = (const float*)d_in[4];
    const float* agk = (const float*)d_in[5];
    const float* xk  = (const float*)d_in[6];
    const float* adk = (const float*)d_in[7];
    const int* epoch = (const int*)d_in[8];
    float* out = (float*)d_out;

    k_init<<<256, 256>>>();
    k_agn<<<128, 128>>>(agq, agk);
    k_global<<<128, 128>>>();
    k_prep_of<<<dim3(4, 128), 256>>>(ofq, ofk);
    k_prep_x<<<dim3(32, 128), 256>>>(xq, xk);
    k_simargmax<<<dim3(8, 8, 64), 256>>>();
    k_dense<<<dim3(8, 64, 2), 256>>>(adq, adk);
    k_final<<<1, 1>>>(epoch, out);
}